// round 1
// baseline (speedup 1.0000x reference)
#include <cuda_runtime.h>
#include <cstdint>

// Problem constants (shapes fixed by the dataset)
#define B 8
#define N 100000
#define V 40
#define NBINS (V * V * V)          // 64000
#define OFFS  (NBINS + 1)          // 64001

// Output layout (float32 elements), tuple flattened + concatenated:
//  [0]                sorted_point_indexes  : B*N            =   800000
//  [800000]           sorted_voxel_hashes   : B*N            =   800000
//  [1600000]          neighbour_voxel_list  : B*V^3*27*3     = 41472000
//  [43072000]         mask                  : B*V^3          =   512000
#define O_IDX  0
#define O_HASH 800000
#define O_NBR  1600000
#define O_MASK 43072000

// ---- scratch (device globals; no allocation allowed) ----
__device__ int g_voxel[B * N];       // voxel bin id per point
__device__ int g_hist[B * OFFS];     // histogram -> exclusive offsets (in place)
__device__ int g_cursor[B * NBINS];  // scatter cursors
__device__ int g_sorted[B * N];      // sorted point indices (per batch)

// ---------------------------------------------------------------------------
__global__ void zero_hist_kernel() {
    int i = blockIdx.x * blockDim.x + threadIdx.x;
    if (i < B * OFFS) g_hist[i] = 0;
}

// Compute voxel bin per point + histogram
__global__ void bin_kernel(const float* __restrict__ pts) {
    int i = blockIdx.x * blockDim.x + threadIdx.x;
    if (i >= B * N) return;
    int b = i / N;
    const float* p = pts + (size_t)i * 3;
    int cx = (int)(p[0] * (float)(V - 1));
    int cy = (int)(p[1] * (float)(V - 1));
    int cz = (int)(p[2] * (float)(V - 1));
    int bin = cx * (V * V) + cy * V + cz;   // lexicographic == hash order
    g_voxel[i] = bin;
    atomicAdd(&g_hist[b * OFFS + bin], 1);
}

// Exclusive scan of 64000 bins per batch (one block per batch, shuffle scan)
__global__ void scan_kernel() {
    int b = blockIdx.x;
    int* cnt = g_hist + b * OFFS;
    int* cur = g_cursor + b * NBINS;
    __shared__ int wsum[32];
    int lane = threadIdx.x & 31;
    int warp = threadIdx.x >> 5;
    int carry = 0;
    for (int base = 0; base < NBINS; base += 1024) {
        int idx = base + threadIdx.x;
        int v = (idx < NBINS) ? cnt[idx] : 0;
        // warp inclusive scan
        int x = v;
        #pragma unroll
        for (int o = 1; o < 32; o <<= 1) {
            int t = __shfl_up_sync(0xFFFFFFFFu, x, o);
            if (lane >= o) x += t;
        }
        if (lane == 31) wsum[warp] = x;
        __syncthreads();
        if (warp == 0) {
            int s = wsum[lane];
            #pragma unroll
            for (int o = 1; o < 32; o <<= 1) {
                int t = __shfl_up_sync(0xFFFFFFFFu, s, o);
                if (lane >= o) s += t;
            }
            wsum[lane] = s;
        }
        __syncthreads();
        int incl = x + (warp > 0 ? wsum[warp - 1] : 0);
        int excl = carry + incl - v;
        if (idx < NBINS) { cnt[idx] = excl; cur[idx] = excl; }
        carry += wsum[31];
        __syncthreads();   // protect wsum reuse next iteration
    }
    if (threadIdx.x == 0) cnt[NBINS] = carry;   // == N
}

// Unstable scatter into bin segments
__global__ void scatter_kernel() {
    int i = blockIdx.x * blockDim.x + threadIdx.x;
    if (i >= B * N) return;
    int b = i / N;
    int n = i - b * N;
    int bin = g_voxel[i];
    int pos = atomicAdd(&g_cursor[b * NBINS + bin], 1);
    g_sorted[b * N + pos] = n;
}

// Per-bin: stable fixup (insertion sort of tiny segment) + write idx/hash/mask
__global__ void finalize_kernel(float* __restrict__ out) {
    int t = blockIdx.x * blockDim.x + threadIdx.x;
    if (t >= B * NBINS) return;
    int b = t / NBINS;
    int bin = t - b * NBINS;
    const int* off = g_hist + b * OFFS;
    int s = off[bin];
    int e = off[bin + 1];
    int* seg = g_sorted + b * N;

    // insertion sort (bins are tiny: Poisson mean ~1.7)
    for (int a = s + 1; a < e; a++) {
        int key = seg[a];
        int j = a - 1;
        while (j >= s && seg[j] > key) { seg[j + 1] = seg[j]; j--; }
        seg[j + 1] = key;
    }

    int cx = bin / (V * V);
    int cy = (bin / V) % V;
    int cz = bin % V;
    float h = (float)(cx * 10000 + cy * 100 + cz);
    for (int j = s; j < e; j++) {
        out[O_IDX  + b * N + j] = (float)seg[j];
        out[O_HASH + b * N + j] = h;
    }
    // mask: 1 for every occupied voxel except the last occupied segment
    out[O_MASK + b * NBINS + bin] = (e > s && e < N) ? 1.0f : 0.0f;
}

// Constant neighbour table: (B, V, V, V, 27, 3)
__global__ void neighbour_kernel(float* __restrict__ out) {
    int t = blockIdx.x * blockDim.x + threadIdx.x;
    const int TOT = B * NBINS * 27;
    if (t >= TOT) return;
    int m = t % 27;
    int r = t / 27;
    int vox = r % NBINS;
    int x = vox / (V * V);
    int y = (vox / V) % V;
    int z = vox % V;
    int dx = m / 9 - 1;
    int dy = (m / 3) % 3 - 1;
    int dz = m % 3 - 1;
    float* p = out + O_NBR + (size_t)t * 3;
    p[0] = (float)(x + dx);
    p[1] = (float)(y + dy);
    p[2] = (float)(z + dz);
}

extern "C" void kernel_launch(void* const* d_in, const int* in_sizes, int n_in,
                              void* d_out, int out_size) {
    const float* pts = (const float*)d_in[0];
    float* out = (float*)d_out;

    zero_hist_kernel<<<(B * OFFS + 255) / 256, 256>>>();
    bin_kernel<<<(B * N + 255) / 256, 256>>>(pts);
    scan_kernel<<<B, 1024>>>();
    scatter_kernel<<<(B * N + 255) / 256, 256>>>();
    finalize_kernel<<<(B * NBINS + 255) / 256, 256>>>(out);
    neighbour_kernel<<<(B * NBINS * 27 + 255) / 256, 256>>>(out);
}

// round 2
// speedup vs baseline: 1.8472x; 1.8472x over previous
#include <cuda_runtime.h>
#include <cstdint>

#define B 8
#define N 100000
#define V 40
#define NBINS (V * V * V)            // 64000
#define NTILES 63                    // ceil(64000/1024)
#define TILE 1024
#define PB_F (NBINS * 81)            // floats per batch in nbr table = 5,184,000
#define PB_F4 (PB_F / 4)             // 1,296,000 float4 per batch

// Output layout (float32 elements):
#define O_IDX  0
#define O_HASH 800000
#define O_NBR  1600000
#define O_MASK 43072000

// ---- scratch (device globals) ----
__device__ int g_voxel[B * N];
__device__ int g_hist[B * NBINS];    // histogram -> exclusive offsets (in place)
__device__ int g_cursor[B * NBINS];
__device__ int g_sorted[B * N];
__device__ int g_tsum[B * NTILES];   // per-tile sums for scan

// ---------------------------------------------------------------------------
__global__ void zero_hist_kernel() {
    int i = blockIdx.x * blockDim.x + threadIdx.x;
    if (i < B * NBINS / 4) ((int4*)g_hist)[i] = make_int4(0, 0, 0, 0);
}

__global__ void bin_kernel(const float* __restrict__ pts) {
    int i = blockIdx.x * blockDim.x + threadIdx.x;
    if (i >= B * N) return;
    int b = i / N;
    const float* p = pts + (size_t)i * 3;
    int cx = (int)(p[0] * (float)(V - 1));
    int cy = (int)(p[1] * (float)(V - 1));
    int cz = (int)(p[2] * (float)(V - 1));
    int bin = cx * (V * V) + cy * V + cz;
    g_voxel[i] = bin;
    atomicAdd(&g_hist[b * NBINS + bin], 1);
}

// ---- 3-phase scan ---------------------------------------------------------
// Phase A: per-tile sums. 504 blocks of 256 threads, 4 bins/thread (int4).
__global__ void scanA_kernel() {
    int b = blockIdx.x / NTILES;
    int t = blockIdx.x % NTILES;
    int tb = t * TILE + threadIdx.x * 4;       // bin index within batch
    int s = 0;
    if (tb < NBINS) {
        int4 v = *(const int4*)(g_hist + b * NBINS + tb);
        s = v.x + v.y + v.z + v.w;
    }
    // warp reduce
    #pragma unroll
    for (int o = 16; o > 0; o >>= 1) s += __shfl_down_sync(0xFFFFFFFFu, s, o);
    __shared__ int ws[8];
    int lane = threadIdx.x & 31, warp = threadIdx.x >> 5;
    if (lane == 0) ws[warp] = s;
    __syncthreads();
    if (threadIdx.x == 0) {
        int tot = 0;
        #pragma unroll
        for (int w = 0; w < 8; w++) tot += ws[w];
        g_tsum[b * NTILES + t] = tot;
    }
}

// Phase B: exclusive scan of the 63 tile sums per batch. One warp per batch.
__global__ void scanB_kernel() {
    int w = threadIdx.x >> 5, lane = threadIdx.x & 31;
    if (w >= B) return;
    int* ts = g_tsum + w * NTILES;
    int v0 = ts[lane];
    int v1 = (lane < NTILES - 32) ? ts[32 + lane] : 0;
    int s0 = v0, s1 = v1;
    #pragma unroll
    for (int o = 1; o < 32; o <<= 1) {
        int t0 = __shfl_up_sync(0xFFFFFFFFu, s0, o);
        int t1 = __shfl_up_sync(0xFFFFFFFFu, s1, o);
        if (lane >= o) { s0 += t0; s1 += t1; }
    }
    int tot0 = __shfl_sync(0xFFFFFFFFu, s0, 31);
    ts[lane] = s0 - v0;
    if (lane < NTILES - 32) ts[32 + lane] = tot0 + s1 - v1;
}

// Phase C: rescan each tile with its offset, write offsets + cursors.
__global__ void scanC_kernel() {
    int b = blockIdx.x / NTILES;
    int t = blockIdx.x % NTILES;
    int tb = t * TILE + threadIdx.x * 4;
    int4 v = make_int4(0, 0, 0, 0);
    if (tb < NBINS) v = *(const int4*)(g_hist + b * NBINS + tb);
    int tsum = v.x + v.y + v.z + v.w;
    // warp inclusive scan of thread sums
    int lane = threadIdx.x & 31, warp = threadIdx.x >> 5;
    int x = tsum;
    #pragma unroll
    for (int o = 1; o < 32; o <<= 1) {
        int tt = __shfl_up_sync(0xFFFFFFFFu, x, o);
        if (lane >= o) x += tt;
    }
    __shared__ int ws[8];
    if (lane == 31) ws[warp] = x;
    __syncthreads();
    int woff = 0;
    #pragma unroll
    for (int w = 0; w < 8; w++) woff += (w < warp) ? ws[w] : 0;
    int texcl = woff + x - tsum;                      // thread's exclusive offset in tile
    int base = g_tsum[b * NTILES + t] + texcl;
    if (tb < NBINS) {
        int4 o4;
        o4.x = base;
        o4.y = base + v.x;
        o4.z = base + v.x + v.y;
        o4.w = base + v.x + v.y + v.z;
        *(int4*)(g_hist + b * NBINS + tb) = o4;
        *(int4*)(g_cursor + b * NBINS + tb) = o4;
    }
}

// ---- scatter: 2 points per thread for MLP --------------------------------
__global__ void scatter_kernel() {
    int t = blockIdx.x * blockDim.x + threadIdx.x;
    #pragma unroll
    for (int k = 0; k < 2; k++) {
        int i = t * 2 + k;
        if (i < B * N) {
            int b = i / N;
            int n = i - b * N;
            int bin = g_voxel[i];
            int pos = atomicAdd(&g_cursor[b * NBINS + bin], 1);
            g_sorted[b * N + pos] = n;
        }
    }
}

// ---- per-bin stable fixup + idx/hash/mask ---------------------------------
__global__ void finalize_kernel(float* __restrict__ out) {
    int t = blockIdx.x * blockDim.x + threadIdx.x;
    if (t >= B * NBINS) return;
    int b = t / NBINS;
    int bin = t - b * NBINS;
    const int* off = g_hist + b * NBINS;
    int s = off[bin];
    int e = (bin == NBINS - 1) ? N : off[bin + 1];
    int* seg = g_sorted + b * N;

    for (int a = s + 1; a < e; a++) {
        int key = seg[a];
        int j = a - 1;
        while (j >= s && seg[j] > key) { seg[j + 1] = seg[j]; j--; }
        seg[j + 1] = key;
    }

    int cx = bin / (V * V);
    int cy = (bin / V) % V;
    int cz = bin % V;
    float h = (float)(cx * 10000 + cy * 100 + cz);
    for (int j = s; j < e; j++) {
        out[O_IDX  + b * N + j] = (float)seg[j];
        out[O_HASH + b * N + j] = h;
    }
    out[O_MASK + b * NBINS + bin] = (e > s && e < N) ? 1.0f : 0.0f;
}

// ---- neighbour table: compute one batch's float4 once, store to 8 batches --
__global__ void neighbour_kernel(float* __restrict__ out) {
    __shared__ int   s_sel[81];
    __shared__ float s_add[81];
    if (threadIdx.x < 81) {
        int j = threadIdx.x;
        int c = j % 3, m = j / 3;
        int d = (c == 0) ? (m / 9 - 1) : (c == 1) ? ((m / 3) % 3 - 1) : (m % 3 - 1);
        s_sel[j] = c;
        s_add[j] = (float)d;
    }
    __syncthreads();

    int q = blockIdx.x * blockDim.x + threadIdx.x;
    if (q >= PB_F4) return;

    int e0  = q * 4;                   // float index within batch
    int vox = e0 / 81;
    int j0  = e0 - vox * 81;
    int x = vox / (V * V);
    int r = vox - x * (V * V);
    int y = r / V;
    int z = r - y * V;
    float xf = (float)x, yf = (float)y, zf = (float)z;
    // coords of vox+1 (used only when the float4 crosses a voxel boundary)
    int zn = z + 1, yn = y, xn = x;
    if (zn == V) { zn = 0; yn = y + 1; if (yn == V) { yn = 0; xn = x + 1; } }
    float xf1 = (float)xn, yf1 = (float)yn, zf1 = (float)zn;

    float4 v;
    float* vp = &v.x;
    #pragma unroll
    for (int k = 0; k < 4; k++) {
        int jk = j0 + k;
        bool w = jk >= 81;
        int jj = w ? jk - 81 : jk;
        int sel = s_sel[jj];
        float cx = (sel == 0) ? (w ? xf1 : xf)
                 : (sel == 1) ? (w ? yf1 : yf)
                              : (w ? zf1 : zf);
        vp[k] = cx + s_add[jj];
    }

    float4* pout = (float4*)(out + O_NBR);
    #pragma unroll
    for (int b = 0; b < B; b++) pout[q + b * PB_F4] = v;
}

// ---------------------------------------------------------------------------
extern "C" void kernel_launch(void* const* d_in, const int* in_sizes, int n_in,
                              void* d_out, int out_size) {
    const float* pts = (const float*)d_in[0];
    float* out = (float*)d_out;

    static cudaStream_t s_side = nullptr;
    static cudaEvent_t ev_fork = nullptr, ev_join = nullptr;
    if (s_side == nullptr) {
        cudaStreamCreateWithFlags(&s_side, cudaStreamNonBlocking);
        cudaEventCreateWithFlags(&ev_fork, cudaEventDisableTiming);
        cudaEventCreateWithFlags(&ev_join, cudaEventDisableTiming);
    }

    // Fork: neighbour table (independent, store-BW bound) on the side stream.
    cudaEventRecord(ev_fork, 0);
    cudaStreamWaitEvent(s_side, ev_fork, 0);
    neighbour_kernel<<<(PB_F4 + 255) / 256, 256, 0, s_side>>>(out);
    cudaEventRecord(ev_join, s_side);

    // Main chain on the default stream.
    zero_hist_kernel<<<(B * NBINS / 4 + 255) / 256, 256>>>();
    bin_kernel<<<(B * N + 255) / 256, 256>>>(pts);
    scanA_kernel<<<B * NTILES, 256>>>();
    scanB_kernel<<<1, 256>>>();
    scanC_kernel<<<B * NTILES, 256>>>();
    scatter_kernel<<<(B * N / 2 + 255) / 256, 256>>>();
    finalize_kernel<<<(B * NBINS + 255) / 256, 256>>>(out);

    // Join.
    cudaStreamWaitEvent(0, ev_join, 0);
}